// round 14
// baseline (speedup 1.0000x reference)
#include <cuda_runtime.h>
#include <math.h>

// Problem constants
#define B_ 256
#define N_ 1024
#define H_ 256
#define K_ 5
#define NEG_SLOPE 0.01f
#define FULLMASK 0xffffffffu

// Per-batch top-K slots: packed u64 = (ord(float) << 32) | (N-1-idx).
// Zero = empty. atomicMax cascade keeps slots sorted descending and holding
// exactly the top-K (distinct keys). Zero-init at module load; pool kernel
// resets them after reading (graph-replay safe).
__device__ unsigned long long g_top[B_ * K_];

static __device__ __forceinline__ float neg_inf() {
    return __int_as_float(0xff800000);
}

// ---------------------------------------------------------------------------
// Kernel 1: per-node max over channels + lock-free top-5 insert per batch.
// One warp per 4 nodes; 8 LDG.128 front-batched (4KB/warp in flight).
// ---------------------------------------------------------------------------
__global__ void __launch_bounds__(256)
node_max_kernel(const float* __restrict__ h, const int* __restrict__ n_nodes) {
    const int gw   = (blockIdx.x * 256 + threadIdx.x) >> 5;  // warp id
    const int lane = threadIdx.x & 31;
    const int base = gw << 2;                 // first of 4 nodes (same batch)
    const int b    = base >> 10;              // N_ = 1024
    const int n0   = base & (N_ - 1);
    const int nn   = __ldg(&n_nodes[b]);
    const float NI = neg_inf();

    if (n0 >= nn) return;                     // whole group masked: no work

    const float4* p = reinterpret_cast<const float4*>(h) + (size_t)base * (H_ / 4);

    float4 va[4], vc[4];
    bool valid[4];
#pragma unroll
    for (int j = 0; j < 4; j++) {
        valid[j] = (n0 + j) < nn;
        if (valid[j]) {
            va[j] = p[(j << 6) + lane];
            vc[j] = p[(j << 6) + lane + 32];
        }
    }

    float m[4];
#pragma unroll
    for (int j = 0; j < 4; j++) {
        if (valid[j]) {
            m[j] = fmaxf(fmaxf(fmaxf(va[j].x, va[j].y), fmaxf(va[j].z, va[j].w)),
                         fmaxf(fmaxf(vc[j].x, vc[j].y), fmaxf(vc[j].z, vc[j].w)));
        } else {
            m[j] = NI;
        }
    }

#pragma unroll
    for (int o = 16; o; o >>= 1) {
#pragma unroll
        for (int j = 0; j < 4; j++)
            m[j] = fmaxf(m[j], __shfl_xor_sync(FULLMASK, m[j], o));
    }

    // lanes 0..3 insert node n0+lane's key (value m[lane]) into g_top[b]
    if (lane < 4) {
        float mv = (lane == 0) ? m[0] : (lane == 1) ? m[1]
                 : (lane == 2) ? m[2] : m[3];
        bool  vl = (n0 + lane) < nn;
        if (vl) {
            unsigned int bits = __float_as_uint(mv);
            unsigned int ord  = (bits & 0x80000000u) ? ~bits
                                                     : (bits | 0x80000000u);
            unsigned long long x =
                ((unsigned long long)ord << 32) |
                (unsigned int)(N_ - 1 - (n0 + lane));

            unsigned long long* slots = &g_top[b * K_];
            // slot[K-1] is monotone non-decreasing: if x <= it now, x can
            // never be top-K -> safe early-out.
            if (x > __ldcg(&slots[K_ - 1])) {
#pragma unroll
                for (int j2 = 0; j2 < K_; j2++) {
                    unsigned long long old = atomicMax(&slots[j2], x);
                    if (old == 0ull) break;   // empty slot filled, none displaced
                    // if old >= x: slot unchanged, x continues down.
                    // if old <  x: x placed, displaced old continues down.
                    x = (old < x) ? old : x;
                }
            }
        }
    }
}

// ---------------------------------------------------------------------------
// Kernel 2 (1 block barrier, minimal critical path):
//  - warps 0..4: read slot wid directly (k-th largest, slots sorted desc),
//    gather row (2x float4/lane), register bitonic sort (8/lane), dot W[:H].
//  - warp 5: cb = dot(q, W[H:2H]).
//  - slots reset to 0 after barrier (graph-replay safe).
//  - all threads: leaky + softmax over K + weighted sum.
// ---------------------------------------------------------------------------
__global__ void __launch_bounds__(256)
pool_attn_kernel(const float* __restrict__ h,
                 const float* __restrict__ q,
                 const float* __restrict__ W,
                 float* __restrict__ out) {
    __shared__ float s_sel[K_][H_];      // sorted selected rows
    __shared__ float s_logit[K_];        // raw dot (pre-cb, pre-leaky)
    __shared__ float s_cb;

    const int b    = blockIdx.x;
    const int t    = threadIdx.x;
    const int wid  = t >> 5;
    const int lane = t & 31;

    if (wid < K_) {
        // k-th largest is simply slot[wid] (cascade keeps slots sorted desc)
        const unsigned long long w = __ldcg(&g_top[b * K_ + wid]);
        const int  node  = (N_ - 1) - (int)(w & 0xffffffffu);
        const bool valid = (unsigned int)(w >> 32) != 0u;   // 0 = empty slot

        // ---- gather row (2 x float4 per lane) ----
        float val[8];
        if (valid) {
            const float4* row4 = reinterpret_cast<const float4*>(
                h + ((size_t)b * N_ + node) * H_);
            float4 r0 = row4[(lane << 1)];
            float4 r1 = row4[(lane << 1) + 1];
            val[0] = r0.x; val[1] = r0.y; val[2] = r0.z; val[3] = r0.w;
            val[4] = r1.x; val[5] = r1.y; val[6] = r1.z; val[7] = r1.w;
        } else {
#pragma unroll
            for (int r = 0; r < 8; r++) val[r] = 0.0f;
        }

        // ---- register bitonic sort, 256 elements, ascending ----
#pragma unroll
        for (int kk = 2; kk <= 256; kk <<= 1) {
#pragma unroll
            for (int j = kk >> 1; j > 0; j >>= 1) {
                if (j >= 8) {
                    int  ld  = j >> 3;
                    bool asc = (((lane << 3) & kk) == 0);
                    bool low = ((lane & ld) == 0);
#pragma unroll
                    for (int r = 0; r < 8; r++) {
                        float other = __shfl_xor_sync(FULLMASK, val[r], ld);
                        val[r] = (low == asc) ? fminf(val[r], other)
                                              : fmaxf(val[r], other);
                    }
                } else {
#pragma unroll
                    for (int r = 0; r < 8; r++) {
                        if ((r & j) == 0) {
                            int  r2  = r | j;
                            bool asc = ((((lane << 3) | r) & kk) == 0);
                            float a = val[r], c = val[r2];
                            float lo = fminf(a, c), hi = fmaxf(a, c);
                            val[r]  = asc ? lo : hi;
                            val[r2] = asc ? hi : lo;
                        }
                    }
                }
            }
        }

        // ---- store sorted row + raw dot with W[:H] ----
        float s = 0.0f;
#pragma unroll
        for (int r = 0; r < 8; r++) {
            int i = (lane << 3) + r;
            s_sel[wid][i] = val[r];
            s += val[r] * W[i];
        }
#pragma unroll
        for (int o = 16; o; o >>= 1)
            s += __shfl_xor_sync(FULLMASK, s, o);
        if (lane == 0) s_logit[wid] = s;
    } else if (wid == K_) {
        // ---- cb = dot(q[b,:], W[H:2H]) ----
        float s = 0.0f;
#pragma unroll
        for (int r = 0; r < 8; r++) {
            int i = (lane << 3) + r;
            s += q[b * H_ + i] * W[H_ + i];
        }
#pragma unroll
        for (int o = 16; o; o >>= 1)
            s += __shfl_xor_sync(FULLMASK, s, o);
        if (lane == 0) s_cb = s;
    }
    __syncthreads();   // all slot reads done; s_sel/s_logit/s_cb ready

    // ---- reset slots for next graph replay (after all reads) ----
    if (t < K_) g_top[b * K_ + t] = 0ull;

    // ---- leaky + softmax over K + weighted sum (thread t owns channel t) ----
    const float cb = s_cb;
    float lg[K_];
#pragma unroll
    for (int k = 0; k < K_; k++) {
        float x = s_logit[k] + cb;
        lg[k] = (x >= 0.0f) ? x : NEG_SLOPE * x;
    }
    float lm = lg[0];
#pragma unroll
    for (int k = 1; k < K_; k++) lm = fmaxf(lm, lg[k]);
    float es = 0.0f;
    float e[K_];
#pragma unroll
    for (int k = 0; k < K_; k++) { e[k] = __expf(lg[k] - lm); es += e[k]; }
    float inv = 1.0f / es;
    float acc = 0.0f;
#pragma unroll
    for (int k = 0; k < K_; k++) acc += (e[k] * inv) * s_sel[k][t];

    out[b * H_ + t] = acc;
}

extern "C" void kernel_launch(void* const* d_in, const int* in_sizes, int n_in,
                              void* d_out, int out_size) {
    const float* h  = (const float*)d_in[0];           // [B, N, H]
    const int*   nn = (const int*)d_in[1];             // [B]
    const float* q  = (const float*)d_in[2];           // [B, H]
    const float* W  = (const float*)d_in[3];           // [1, 2H]
    float*       o  = (float*)d_out;                   // [B, H]

    (void)in_sizes; (void)n_in; (void)out_size;

    // Kernel 1: 4 nodes per warp, 8 warps/block -> 32 nodes/block
    node_max_kernel<<<(B_ * N_) / 32, 256>>>(h, nn);
    // Kernel 2: one block per batch
    pool_attn_kernel<<<B_, 256>>>(h, q, W, o);
}

// round 16
// speedup vs baseline: 3.4232x; 3.4232x over previous
#include <cuda_runtime.h>
#include <math.h>

// Problem constants
#define B_ 256
#define N_ 1024
#define H_ 256
#define K_ 5
#define NEG_SLOPE 0.01f
#define FULLMASK 0xffffffffu
#define BLOCKS_PER_B 32          // 32 nodes per block

// Per-block sorted top-5 candidates: packed u64 = (ord(float)<<32)|(N-1-idx),
// idx = WITHIN-BATCH node index. Batch b's candidates: g_cand[b*160 .. +160).
__device__ unsigned long long g_cand[B_ * BLOCKS_PER_B * K_];

static __device__ __forceinline__ float neg_inf() {
    return __int_as_float(0xff800000);
}

static __device__ __forceinline__ unsigned long long
warp_max_u64(unsigned long long w) {
#pragma unroll
    for (int o = 16; o; o >>= 1) {
        unsigned long long ow = __shfl_xor_sync(FULLMASK, w, o);
        if (ow > w) w = ow;
    }
    return w;
}

// idx MUST be the within-batch node index in [0, N_).
static __device__ __forceinline__ unsigned long long
pack_key(float v, int idx) {
    unsigned int bits = __float_as_uint(v);
    unsigned int ord  = (bits & 0x80000000u) ? ~bits : (bits | 0x80000000u);
    return ((unsigned long long)ord << 32) | (unsigned int)(N_ - 1 - idx);
}

// ---------------------------------------------------------------------------
// Kernel 1: per-node max over channels (4 nodes/warp, 8 LDG.128 front-batched)
// + per-block top-5 (warp-0 tournament over the block's 32 keys) -> g_cand.
// Masked nodes contribute packed(-inf) keys (no loads). No atomics, no fences.
// ---------------------------------------------------------------------------
__global__ void __launch_bounds__(256)
node_max_kernel(const float* __restrict__ h, const int* __restrict__ n_nodes) {
    __shared__ unsigned long long s_bk[BLOCKS_PER_B];   // 32 packed keys

    const int wid  = threadIdx.x >> 5;
    const int lane = threadIdx.x & 31;
    const int base = blockIdx.x * BLOCKS_PER_B + (wid << 2); // global, 4/warp
    const int b    = blockIdx.x >> 5;            // 32 blocks per batch
    const int n0   = base & (N_ - 1);            // within-batch index
    const int nn   = __ldg(&n_nodes[b]);
    const float NI = neg_inf();

    float m[4];
    if (n0 >= nn) {
#pragma unroll
        for (int j = 0; j < 4; j++) m[j] = NI;
    } else {
        const float4* p = reinterpret_cast<const float4*>(h) +
                          (size_t)base * (H_ / 4);
        float4 va[4], vc[4];
        bool valid[4];
#pragma unroll
        for (int j = 0; j < 4; j++) {
            valid[j] = (n0 + j) < nn;
            if (valid[j]) {
                va[j] = p[(j << 6) + lane];
                vc[j] = p[(j << 6) + lane + 32];
            }
        }
#pragma unroll
        for (int j = 0; j < 4; j++) {
            m[j] = valid[j]
                 ? fmaxf(fmaxf(fmaxf(va[j].x, va[j].y), fmaxf(va[j].z, va[j].w)),
                         fmaxf(fmaxf(vc[j].x, vc[j].y), fmaxf(vc[j].z, vc[j].w)))
                 : NI;
        }
#pragma unroll
        for (int o = 16; o; o >>= 1) {
#pragma unroll
            for (int j = 0; j < 4; j++)
                m[j] = fmaxf(m[j], __shfl_xor_sync(FULLMASK, m[j], o));
        }
    }

    if (lane < 4) {
        float mv = (lane == 0) ? m[0] : (lane == 1) ? m[1]
                 : (lane == 2) ? m[2] : m[3];
        // FIX: pack the WITHIN-BATCH index (n0 + lane), not the global one.
        s_bk[(wid << 2) + lane] = pack_key(mv, n0 + lane);
    }
    __syncthreads();

    // warp 0: top-5 of the block's 32 keys (distinct => consume-by-zero safe)
    if (wid == 0) {
        unsigned long long x = s_bk[lane];
        unsigned long long* dst = &g_cand[(size_t)blockIdx.x * K_];
#pragma unroll
        for (int k = 0; k < K_; k++) {
            unsigned long long w = warp_max_u64(x);
            if (x == w) x = 0ull;
            if (lane == 0) dst[k] = w;     // sorted descending
        }
    }
}

// ---------------------------------------------------------------------------
// Kernel 2 (1 block barrier):
//  - warps 0..4: merge the batch's 160 candidates (32 sorted 5-lists, one per
//    lane, pointer-consume) with wid+1 butterfly rounds; warp wid exits at its
//    round, gathers its row (2x float4/lane), register bitonic sort, dot W[:H].
//  - warp 5: cb = dot(q, W[H:2H]).
//  - all threads: leaky + softmax over K + weighted sum.
// ---------------------------------------------------------------------------
__global__ void __launch_bounds__(256)
pool_attn_kernel(const float* __restrict__ h,
                 const float* __restrict__ q,
                 const float* __restrict__ W,
                 float* __restrict__ out) {
    __shared__ float s_sel[K_][H_];      // sorted selected rows
    __shared__ float s_logit[K_];        // raw dot (pre-cb, pre-leaky)
    __shared__ float s_cb;

    const int b    = blockIdx.x;
    const int t    = threadIdx.x;
    const int wid  = t >> 5;
    const int lane = t & 31;

    if (wid < K_) {
        // lane holds block-`lane`'s sorted top-5 list
        const unsigned long long* cl =
            &g_cand[((size_t)b * BLOCKS_PER_B + lane) * K_];
        unsigned long long L[K_];
#pragma unroll
        for (int j = 0; j < K_; j++) L[j] = __ldg(&cl[j]);

        int p = 0;
        unsigned long long w = 0ull;
        for (int k = 0; k <= wid; k++) {
            w = warp_max_u64((p < K_) ? L[p] : 0ull);
            if (p < K_ && L[p] == w) p++;       // unique winner consumed
        }
        const int  node  = (N_ - 1) - (int)(w & 0xffffffffu);  // in [0, N_)
        const bool valid = (unsigned int)(w >> 32) > 0x007fffffu; // > ord(-inf)

        // ---- gather row (2 x float4 per lane) ----
        float val[8];
        if (valid) {
            const float4* row4 = reinterpret_cast<const float4*>(
                h + ((size_t)b * N_ + node) * H_);
            float4 r0 = row4[(lane << 1)];
            float4 r1 = row4[(lane << 1) + 1];
            val[0] = r0.x; val[1] = r0.y; val[2] = r0.z; val[3] = r0.w;
            val[4] = r1.x; val[5] = r1.y; val[6] = r1.z; val[7] = r1.w;
        } else {
#pragma unroll
            for (int r = 0; r < 8; r++) val[r] = 0.0f;
        }

        // ---- register bitonic sort, 256 elements, ascending ----
        // element v = lane*8 + r lives in val[r]
#pragma unroll
        for (int kk = 2; kk <= 256; kk <<= 1) {
#pragma unroll
            for (int j = kk >> 1; j > 0; j >>= 1) {
                if (j >= 8) {
                    int  ld  = j >> 3;
                    bool asc = (((lane << 3) & kk) == 0);
                    bool low = ((lane & ld) == 0);
#pragma unroll
                    for (int r = 0; r < 8; r++) {
                        float other = __shfl_xor_sync(FULLMASK, val[r], ld);
                        val[r] = (low == asc) ? fminf(val[r], other)
                                              : fmaxf(val[r], other);
                    }
                } else {
#pragma unroll
                    for (int r = 0; r < 8; r++) {
                        if ((r & j) == 0) {
                            int  r2  = r | j;
                            bool asc = ((((lane << 3) | r) & kk) == 0);
                            float a = val[r], c = val[r2];
                            float lo = fminf(a, c), hi = fmaxf(a, c);
                            val[r]  = asc ? lo : hi;
                            val[r2] = asc ? hi : lo;
                        }
                    }
                }
            }
        }

        // ---- store sorted row + raw dot with W[:H] ----
        float s = 0.0f;
#pragma unroll
        for (int r = 0; r < 8; r++) {
            int i = (lane << 3) + r;
            s_sel[wid][i] = val[r];
            s += val[r] * W[i];
        }
#pragma unroll
        for (int o = 16; o; o >>= 1)
            s += __shfl_xor_sync(FULLMASK, s, o);
        if (lane == 0) s_logit[wid] = s;
    } else if (wid == K_) {
        // ---- cb = dot(q[b,:], W[H:2H]) ----
        float s = 0.0f;
#pragma unroll
        for (int r = 0; r < 8; r++) {
            int i = (lane << 3) + r;
            s += q[b * H_ + i] * W[H_ + i];
        }
#pragma unroll
        for (int o = 16; o; o >>= 1)
            s += __shfl_xor_sync(FULLMASK, s, o);
        if (lane == 0) s_cb = s;
    }
    __syncthreads();

    // ---- leaky + softmax over K + weighted sum (thread t owns channel t) ----
    const float cb = s_cb;
    float lg[K_];
#pragma unroll
    for (int k = 0; k < K_; k++) {
        float x = s_logit[k] + cb;
        lg[k] = (x >= 0.0f) ? x : NEG_SLOPE * x;
    }
    float lm = lg[0];
#pragma unroll
    for (int k = 1; k < K_; k++) lm = fmaxf(lm, lg[k]);
    float es = 0.0f;
    float e[K_];
#pragma unroll
    for (int k = 0; k < K_; k++) { e[k] = __expf(lg[k] - lm); es += e[k]; }
    float inv = 1.0f / es;
    float acc = 0.0f;
#pragma unroll
    for (int k = 0; k < K_; k++) acc += (e[k] * inv) * s_sel[k][t];

    out[b * H_ + t] = acc;
}

extern "C" void kernel_launch(void* const* d_in, const int* in_sizes, int n_in,
                              void* d_out, int out_size) {
    const float* h  = (const float*)d_in[0];           // [B, N, H]
    const int*   nn = (const int*)d_in[1];             // [B]
    const float* q  = (const float*)d_in[2];           // [B, H]
    const float* W  = (const float*)d_in[3];           // [1, 2H]
    float*       o  = (float*)d_out;                   // [B, H]

    (void)in_sizes; (void)n_in; (void)out_size;

    // Kernel 1: 32 nodes per block (4 per warp), block top-5 -> g_cand
    node_max_kernel<<<B_ * BLOCKS_PER_B, 256>>>(h, nn);
    // Kernel 2: one block per batch
    pool_attn_kernel<<<B_, 256>>>(h, q, W, o);
}